// round 12
// baseline (speedup 1.0000x reference)
#include <cuda_runtime.h>
#include <cuda_bf16.h>
#include <cstdint>

// Problem constants
#define NB   16
#define TT   2048
#define FIN  64
#define NN   24
#define HH   64
#define BT   (NB*TT)            // 32768
#define NH   (NN*HH)            // 1536
#define TOK  16                 // tokens per attn block
#define THR  512
#define AGRID (BT/TOK)          // 2048
#define GTOK 128                // tokens per gemm block
#define GGRID (BT/GTOK)         // 256
#define ALPHA 0.2f
#define NEGINF (-9.0e15f)
#define XS   17                 // padded sX stride (attn kernel)
#define XS2  132                // padded sX stride (gemm kernel, conflict-free frag build)

// ---------------- device globals (no allocs) ----------------
__device__ __align__(16) float g_Wc[FIN*NH];    // [f][col], col = n*64+k
__device__ __align__(16) float g_bc[NH];
__device__ __align__(16) float g_ca1[FIN*NN];
__device__ __align__(16) float g_ca2[FIN*NN];
__device__ float g_cb1[NN];
__device__ float g_cb2[NN];
// B fragments for mma.m16n8k16, pre-split bf16 (term0=hi, term1=lo), fragment-ordered:
// index = ((ct*4 + ks)*2 + term)*32 + lane, each 8B = {b0, b1}
__device__ __align__(16) unsigned long long g_Wfrag[192*4*2*32];   // 384KB
__device__ __align__(16) float g_Wh[(size_t)BT*NH];                // 192MB scratch

// ---------------- packed fp32x2 helpers ----------------
__device__ __forceinline__ unsigned long long pack2(float lo, float hi) {
    unsigned long long r;
    asm("mov.b64 %0, {%1, %2};" : "=l"(r) : "f"(lo), "f"(hi));
    return r;
}
__device__ __forceinline__ void unpack2u(unsigned long long v, uint32_t& lo, uint32_t& hi) {
    asm("mov.b64 {%0, %1}, %2;" : "=r"(lo), "=r"(hi) : "l"(v));
}
__device__ __forceinline__ void unpack2(unsigned long long v, float& lo, float& hi) {
    asm("mov.b64 {%0, %1}, %2;" : "=f"(lo), "=f"(hi) : "l"(v));
}
#define FMA2(acc, a, b) asm("fma.rn.f32x2 %0, %1, %2, %0;" : "+l"(acc) : "l"(a), "l"(b))

// ---------------- warp mma m16n8k16 bf16 ----------------
__device__ __forceinline__ void mma16816(float& d0, float& d1, float& d2, float& d3,
                                         uint32_t a0, uint32_t a1, uint32_t a2, uint32_t a3,
                                         uint32_t b0, uint32_t b1) {
    asm("mma.sync.aligned.m16n8k16.row.col.f32.bf16.bf16.f32 "
        "{%0,%1,%2,%3}, {%4,%5,%6,%7}, {%8,%9}, {%0,%1,%2,%3};"
        : "+f"(d0), "+f"(d1), "+f"(d2), "+f"(d3)
        : "r"(a0), "r"(a1), "r"(a2), "r"(a3), "r"(b0), "r"(b1));
}
__device__ __forceinline__ uint32_t bpack(__nv_bfloat16 x, __nv_bfloat16 y) {
    __nv_bfloat162 p; p.x = x; p.y = y;
    return *(uint32_t*)&p;
}

// ---------------- cp.async ----------------
__device__ __forceinline__ uint32_t smem_u32(const void* p) {
    return (uint32_t)__cvta_generic_to_shared(p);
}
#define CP_ASYNC16(dst, src) \
    asm volatile("cp.async.cg.shared.global [%0], [%1], 16;" :: "r"(dst), "l"(src) : "memory")
#define CP_COMMIT() asm volatile("cp.async.commit_group;" ::: "memory")
#define CP_WAIT0()  asm volatile("cp.async.wait_group 0;" ::: "memory")

// ---------------- precompute: grid (64, 4) for latency hiding ----------------
__global__ void __launch_bounds__(256)
k_pre(const float* __restrict__ Wp, const float* __restrict__ bp,
      const float* __restrict__ W,  const float* __restrict__ a) {
    __shared__ float sW[HH*HH];
    __shared__ float sWp[NH];
    __shared__ float swa1[HH], swa2[HH];
    const int f = blockIdx.x, q = blockIdx.y, tid = threadIdx.x;
    for (int i = tid; i < HH*HH; i += 256) sW[i] = W[i];
    for (int i = tid; i < NH;    i += 256) sWp[i] = Wp[f*NH + i];
    __syncthreads();
    if (q == 0 && tid < HH) {
        float s1 = 0.f, s2 = 0.f;
        #pragma unroll 8
        for (int k = 0; k < HH; k++) {
            float wv = sW[tid*HH + k];
            s1 = fmaf(wv, a[k],      s1);
            s2 = fmaf(wv, a[HH + k], s2);
        }
        swa1[tid] = s1; swa2[tid] = s2;
    }
    __syncthreads();
    // Wc quarter-slice
    for (int o = q*384 + tid; o < q*384 + 384; o += 256) {
        int n = o >> 6, k = o & 63;
        float s = 0.f;
        #pragma unroll 8
        for (int j = 0; j < HH; j++) s = fmaf(sWp[n*HH + j], sW[j*HH + k], s);
        g_Wc[f*NH + o] = s;
    }
    if (q == 0) {
        if (tid < NN) {
            float s1 = 0.f, s2 = 0.f;
            for (int j = 0; j < HH; j++) {
                float wv = sWp[tid*HH + j];
                s1 = fmaf(wv, swa1[j], s1);
                s2 = fmaf(wv, swa2[j], s2);
            }
            g_ca1[f*NN + tid] = s1;
            g_ca2[f*NN + tid] = s2;
        }
        if (tid >= 32 && tid < 32 + NN) {
            int c = f*NN + (tid - 32);
            int n = c >> 6, k = c & 63;
            float s = 0.f;
            #pragma unroll 8
            for (int j = 0; j < HH; j++) s = fmaf(bp[n*HH + j], sW[j*HH + k], s);
            g_bc[c] = s;
        }
        if (f == 0 && tid >= 64 && tid < 64 + NN) {
            int n = tid - 64;
            float s1 = 0.f, s2 = 0.f;
            for (int j = 0; j < HH; j++) {
                float b = bp[n*HH + j];
                s1 = fmaf(b, swa1[j], s1);
                s2 = fmaf(b, swa2[j], s2);
            }
            g_cb1[n] = s1; g_cb2[n] = s2;
        }
    }
}

// ---------------- B-fragment precompute (unchanged, validated R11) ----------------
__global__ void k_frag() {
    int u = blockIdx.x * 256 + threadIdx.x;
    if (u >= 192*4*2*32) return;
    int lane = u & 31;
    int term = (u >> 5) & 1;
    int ks   = (u >> 6) & 3;
    int ct   = u >> 8;
    int col = ct*8 + (lane >> 2);
    int f0  = ks*16 + (lane & 3)*2;
    __nv_bfloat16 e[4];
    #pragma unroll
    for (int r = 0; r < 4; r++) {
        int f = f0 + (r >> 1)*8 + (r & 1);
        float v = g_Wc[f*NH + col];
        __nv_bfloat16 hi = __float2bfloat16(v);
        e[r] = term ? __float2bfloat16(v - __bfloat162float(hi)) : hi;
    }
    uint32_t b0 = bpack(e[0], e[1]);
    uint32_t b1 = bpack(e[2], e[3]);
    g_Wfrag[u] = ((unsigned long long)b1 << 32) | b0;
}

// ---------------- GEMM kernel: g_Wh = x @ Wc + bc, M=128/block ----------------
// 16 warps = 8 m-tiles x 2 nt-halves. Fragment reads shared 8-ways via L1
// (all m-warps sweep nt in identical order). 3-term bf16 split (as R11).
__global__ void __launch_bounds__(512)
k_gemm(const float* __restrict__ x) {
    __shared__ float sX2[FIN*XS2];     // 33792B, f-major padded
    __shared__ float sBC[NH];          // 6144B
    const int tid = threadIdx.x;
    const int tok0 = blockIdx.x * GTOK;

    const float* xb = x + (size_t)tok0 * FIN;
    for (int i = tid; i < GTOK*FIN; i += 512) {
        int t = i >> 6, f = i & 63;
        sX2[f*XS2 + t] = xb[i];
    }
    for (int i = tid; i < NH; i += 512) sBC[i] = g_bc[i];
    __syncthreads();

    const int w = tid >> 5, lane = tid & 31;
    const int m    = w & 7;            // m-tile (16 tokens)
    const int half = w >> 3;           // nt half: cols [half*768, +768)
    const int t0 = lane >> 2;
    const int fq = (lane & 3) * 2;

    // A fragments for this m-tile (hi & lo split)
    uint32_t ah[4][4], al[4][4];
    #pragma unroll
    for (int ks = 0; ks < 4; ks++) {
        #pragma unroll
        for (int r = 0; r < 4; r++) {
            int f = ks*16 + fq + (r >> 1)*8;
            int t = m*16 + t0 + (r & 1)*8;
            float v0 = sX2[f*XS2 + t];
            float v1 = sX2[(f+1)*XS2 + t];
            __nv_bfloat16 h0 = __float2bfloat16(v0);
            __nv_bfloat16 h1 = __float2bfloat16(v1);
            ah[ks][r] = bpack(h0, h1);
            al[ks][r] = bpack(__float2bfloat16(v0 - __bfloat162float(h0)),
                              __float2bfloat16(v1 - __bfloat162float(h1)));
        }
    }

    float* whr0 = g_Wh + (size_t)(tok0 + m*16 + t0)     * NH;
    float* whr8 = g_Wh + (size_t)(tok0 + m*16 + t0 + 8) * NH;

    #pragma unroll 2
    for (int nt = 0; nt < 96; nt++) {
        const int ct = half*96 + nt;
        float d0 = 0.f, d1 = 0.f, d2 = 0.f, d3 = 0.f;
        #pragma unroll
        for (int ks = 0; ks < 4; ks++) {
            unsigned long long bh = __ldg(&g_Wfrag[((ct*4 + ks)*2 + 0)*32 + lane]);
            unsigned long long bl = __ldg(&g_Wfrag[((ct*4 + ks)*2 + 1)*32 + lane]);
            uint32_t bh0, bh1, bl0, bl1;
            unpack2u(bh, bh0, bh1);
            unpack2u(bl, bl0, bl1);
            mma16816(d0, d1, d2, d3, ah[ks][0], ah[ks][1], ah[ks][2], ah[ks][3], bh0, bh1);
            mma16816(d0, d1, d2, d3, ah[ks][0], ah[ks][1], ah[ks][2], ah[ks][3], bl0, bl1);
            mma16816(d0, d1, d2, d3, al[ks][0], al[ks][1], al[ks][2], al[ks][3], bh0, bh1);
        }
        const int col = ct*8 + fq;
        float b0 = sBC[col], b1 = sBC[col + 1];
        *(unsigned long long*)&whr0[col] = pack2(d0 + b0, d1 + b1);
        *(unsigned long long*)&whr8[col] = pack2(d2 + b0, d3 + b1);
    }
}

// ---------------- attention kernel ----------------
// smem layout (bytes):
//  sX    @ 0      : 64 x 17 f32                       4608
//  sCa1  @ 4608   : 1536 f32                          6144
//  sCa2  @ 10752  : 1536 f32                          6144
//  sCb1  @ 16896  : 24 f32                            96
//  sCb2  @ 16992  : 24 f32                            96
//  sF1   @ 17088  : 16x24 f32                         1536
//  sF2   @ 18624  : 16x24 f32                         1536
//  sAdj  @ 20160  : 576 i32                           2304
//  sAttn @ 22464  : 16x24x24 f32                      36864
//  sWh   @ 59328  : 16x1536 f32                       98304
#define SMEM_BYTES 157632

__global__ void __launch_bounds__(THR, 1)
k_attn(const float* __restrict__ x, const int* __restrict__ adj,
       float* __restrict__ out) {
    extern __shared__ char smem[];
    float* sX    = (float*)(smem);
    float* sCa1  = (float*)(smem + 4608);
    float* sCa2  = (float*)(smem + 10752);
    float* sCb1  = (float*)(smem + 16896);
    float* sCb2  = (float*)(smem + 16992);
    float* sF1   = (float*)(smem + 17088);
    float* sF2   = (float*)(smem + 18624);
    int*   sAdj  = (int*)  (smem + 20160);
    float* sAttn = (float*)(smem + 22464);
    float* sWh   = (float*)(smem + 59328);

    const int tid = threadIdx.x;
    const int tok0 = blockIdx.x * TOK;
    const float* xb = x + (size_t)tok0 * FIN;

    // ---- stage Wh tile first: overlaps with f1/f2 + softmax below ----
    {
        const uint32_t whdst = smem_u32(sWh);
        const float4* whsrc = (const float4*)(g_Wh + (size_t)tok0 * NH);
        #pragma unroll
        for (int s = 0; s < (TOK*NH/4)/THR; s++) {     // 12 x 16B per thread
            int u = tid + s*THR;
            CP_ASYNC16(whdst + u*16, whsrc + u);
        }
        CP_COMMIT();
    }

    // ---- other loads ----
    for (int i = tid; i < TOK*FIN; i += THR) {
        int t = i >> 6, f = i & 63;
        sX[f*XS + t] = xb[i];
    }
    for (int i = tid; i < FIN*NN; i += THR) { sCa1[i] = g_ca1[i]; sCa2[i] = g_ca2[i]; }
    if (tid < NN) { sCb1[tid] = g_cb1[tid]; sCb2[tid] = g_cb2[tid]; }
    for (int i = tid; i < NN*NN; i += THR) sAdj[i] = adj[i];
    __syncthreads();

    // ---- f1/f2 ----
    if (tid < TOK*NN) {
        int t = tid / NN, n = tid % NN;
        float s1 = sCb1[n], s2 = sCb2[n];
        #pragma unroll 8
        for (int f = 0; f < FIN; f++) {
            float xv = sX[f*XS + t];
            s1 = fmaf(xv, sCa1[f*NN + n], s1);
            s2 = fmaf(xv, sCa2[f*NN + n], s2);
        }
        sF1[t*NN + n] = s1;
        sF2[t*NN + n] = s2;
    }
    __syncthreads();

    // ---- softmax rows ----
    if (tid < TOK*NN) {
        int t = tid / NN, i = tid % NN;
        float f1v = sF1[t*NN + i];
        float ev[NN];
        float m = -3.0e38f;
        #pragma unroll
        for (int j = 0; j < NN; j++) {
            float e = f1v + sF2[t*NN + j];
            e = e > 0.f ? e : ALPHA * e;
            e = (sAdj[i*NN + j] > 0) ? e : NEGINF;
            ev[j] = e;
            m = fmaxf(m, e);
        }
        float sum = 0.f;
        #pragma unroll
        for (int j = 0; j < NN; j++) { float p = __expf(ev[j] - m); ev[j] = p; sum += p; }
        float inv = 1.0f / sum;
        #pragma unroll
        for (int j = 0; j < NN; j++) sAttn[t*576 + i*NN + j] = ev[j] * inv;
    }

    CP_WAIT0();
    __syncthreads();

    // ---- phase 2: out[t][k] = mean_i elu( sum_j attn[t][i][j]*Wh[t][j][k] ) ----
    {
        const int t = tid >> 5;        // 0..15 (uniform per warp)
        const int g = tid & 31;        // k in {g, g+32}
        const float* whb = sWh + (size_t)t*NH;
        unsigned long long wj[12][2];
        #pragma unroll
        for (int m = 0; m < 12; m++) {
            wj[m][0] = pack2(whb[(2*m)*HH + g],      whb[(2*m+1)*HH + g]);
            wj[m][1] = pack2(whb[(2*m)*HH + g + 32], whb[(2*m+1)*HH + g + 32]);
        }
        const unsigned long long* ap = (const unsigned long long*)(sAttn + t*576);
        float o0 = 0.f, o1 = 0.f;
        #pragma unroll 2
        for (int i = 0; i < NN; i++) {
            unsigned long long s0 = 0ull, s1 = 0ull;
            #pragma unroll
            for (int m = 0; m < 12; m++) {
                unsigned long long av = ap[i*12 + m];
                FMA2(s0, av, wj[m][0]);
                FMA2(s1, av, wj[m][1]);
            }
            float a0, b0, a1, b1;
            unpack2(s0, a0, b0);
            unpack2(s1, a1, b1);
            float v0 = a0 + b0, v1 = a1 + b1;
            o0 += (v0 > 0.f) ? v0 : (__expf(v0) - 1.f);
            o1 += (v1 > 0.f) ? v1 : (__expf(v1) - 1.f);
        }
        const float sc = 1.0f / (float)NN;
        float* ob = out + (size_t)(tok0 + t) * HH;
        ob[g]      = o0 * sc;
        ob[g + 32] = o1 * sc;
    }
}

// ---------------- launch ----------------
extern "C" void kernel_launch(void* const* d_in, const int* in_sizes, int n_in,
                              void* d_out, int out_size) {
    const float* x   = (const float*)d_in[0];
    const int*   adj = (const int*)  d_in[1];
    const float* Wp  = (const float*)d_in[2];
    const float* bp  = (const float*)d_in[3];
    const float* W   = (const float*)d_in[4];
    const float* a   = (const float*)d_in[5];
    float* out = (float*)d_out;

    k_pre<<<dim3(FIN, 4), 256>>>(Wp, bp, W, a);
    k_frag<<<192, 256>>>();
    k_gemm<<<GGRID, 512>>>(x);

    cudaFuncSetAttribute(k_attn, cudaFuncAttributeMaxDynamicSharedMemorySize, SMEM_BYTES);
    k_attn<<<AGRID, THR, SMEM_BYTES>>>(x, adj, out);
}

// round 13
// speedup vs baseline: 1.4365x; 1.4365x over previous
#include <cuda_runtime.h>
#include <cuda_bf16.h>
#include <cstdint>

// Problem constants
#define NB   16
#define TT   2048
#define FIN  64
#define NN   24
#define HH   64
#define BT   (NB*TT)            // 32768
#define NH   (NN*HH)            // 1536
#define TOK  16                 // tokens per tile
#define THR  512
#define NTILE (BT/TOK)          // 2048
#define PGRID 152               // persistent blocks (GB300 SM count)
#define ALPHA 0.2f
#define NEGINF (-9.0e15f)
#define XS3  68                 // token-major sX row stride (floats, 16B-multiple)

// ---------------- device globals (no allocs) ----------------
__device__ __align__(16) float g_Wc[FIN*NH];    // [f][col], col = n*64+k
__device__ __align__(16) float g_bc[NH];
__device__ __align__(16) float g_ca1[FIN*NN];
__device__ __align__(16) float g_ca2[FIN*NN];
__device__ float g_cb1[NN];
__device__ float g_cb2[NN];
// B fragments for mma.m16n8k16, pre-split bf16 (term0=hi, term1=lo), fragment-ordered:
// index = ((ct*4 + ks)*2 + term)*32 + lane, each 8B = {b0, b1}
__device__ __align__(16) unsigned long long g_Wfrag[192*4*2*32];   // 384KB

// ---------------- packed fp32x2 helpers ----------------
__device__ __forceinline__ unsigned long long pack2(float lo, float hi) {
    unsigned long long r;
    asm("mov.b64 %0, {%1, %2};" : "=l"(r) : "f"(lo), "f"(hi));
    return r;
}
__device__ __forceinline__ void unpack2u(unsigned long long v, uint32_t& lo, uint32_t& hi) {
    asm("mov.b64 {%0, %1}, %2;" : "=r"(lo), "=r"(hi) : "l"(v));
}
__device__ __forceinline__ void unpack2(unsigned long long v, float& lo, float& hi) {
    asm("mov.b64 {%0, %1}, %2;" : "=f"(lo), "=f"(hi) : "l"(v));
}
#define FMA2(acc, a, b) asm("fma.rn.f32x2 %0, %1, %2, %0;" : "+l"(acc) : "l"(a), "l"(b))

// ---------------- warp mma m16n8k16 bf16 ----------------
__device__ __forceinline__ void mma16816(float& d0, float& d1, float& d2, float& d3,
                                         uint32_t a0, uint32_t a1, uint32_t a2, uint32_t a3,
                                         uint32_t b0, uint32_t b1) {
    asm("mma.sync.aligned.m16n8k16.row.col.f32.bf16.bf16.f32 "
        "{%0,%1,%2,%3}, {%4,%5,%6,%7}, {%8,%9}, {%0,%1,%2,%3};"
        : "+f"(d0), "+f"(d1), "+f"(d2), "+f"(d3)
        : "r"(a0), "r"(a1), "r"(a2), "r"(a3), "r"(b0), "r"(b1));
}
__device__ __forceinline__ uint32_t bpack(__nv_bfloat16 x, __nv_bfloat16 y) {
    __nv_bfloat162 p; p.x = x; p.y = y;
    return *(uint32_t*)&p;
}

// ---------------- cp.async ----------------
__device__ __forceinline__ uint32_t smem_u32(const void* p) {
    return (uint32_t)__cvta_generic_to_shared(p);
}
#define CP_ASYNC16(dst, src) \
    asm volatile("cp.async.cg.shared.global [%0], [%1], 16;" :: "r"(dst), "l"(src) : "memory")
#define CP_COMMIT() asm volatile("cp.async.commit_group;" ::: "memory")
#define CP_WAIT1()  asm volatile("cp.async.wait_group 1;" ::: "memory")

// ---------------- precompute: grid (64, 4) ----------------
__global__ void __launch_bounds__(256)
k_pre(const float* __restrict__ Wp, const float* __restrict__ bp,
      const float* __restrict__ W,  const float* __restrict__ a) {
    __shared__ float sW[HH*HH];
    __shared__ float sWp[NH];
    __shared__ float swa1[HH], swa2[HH];
    const int f = blockIdx.x, q = blockIdx.y, tid = threadIdx.x;
    for (int i = tid; i < HH*HH; i += 256) sW[i] = W[i];
    for (int i = tid; i < NH;    i += 256) sWp[i] = Wp[f*NH + i];
    __syncthreads();
    if (q == 0 && tid < HH) {
        float s1 = 0.f, s2 = 0.f;
        #pragma unroll 8
        for (int k = 0; k < HH; k++) {
            float wv = sW[tid*HH + k];
            s1 = fmaf(wv, a[k],      s1);
            s2 = fmaf(wv, a[HH + k], s2);
        }
        swa1[tid] = s1; swa2[tid] = s2;
    }
    __syncthreads();
    for (int o = q*384 + tid; o < q*384 + 384; o += 256) {
        int n = o >> 6, k = o & 63;
        float s = 0.f;
        #pragma unroll 8
        for (int j = 0; j < HH; j++) s = fmaf(sWp[n*HH + j], sW[j*HH + k], s);
        g_Wc[f*NH + o] = s;
    }
    if (q == 0) {
        if (tid < NN) {
            float s1 = 0.f, s2 = 0.f;
            for (int j = 0; j < HH; j++) {
                float wv = sWp[tid*HH + j];
                s1 = fmaf(wv, swa1[j], s1);
                s2 = fmaf(wv, swa2[j], s2);
            }
            g_ca1[f*NN + tid] = s1;
            g_ca2[f*NN + tid] = s2;
        }
        if (tid >= 32 && tid < 32 + NN) {
            int c = f*NN + (tid - 32);
            int n = c >> 6, k = c & 63;
            float s = 0.f;
            #pragma unroll 8
            for (int j = 0; j < HH; j++) s = fmaf(bp[n*HH + j], sW[j*HH + k], s);
            g_bc[c] = s;
        }
        if (f == 0 && tid >= 64 && tid < 64 + NN) {
            int n = tid - 64;
            float s1 = 0.f, s2 = 0.f;
            for (int j = 0; j < HH; j++) {
                float b = bp[n*HH + j];
                s1 = fmaf(b, swa1[j], s1);
                s2 = fmaf(b, swa2[j], s2);
            }
            g_cb1[n] = s1; g_cb2[n] = s2;
        }
    }
}

// ---------------- B-fragment precompute (validated) ----------------
__global__ void k_frag() {
    int u = blockIdx.x * 256 + threadIdx.x;
    if (u >= 192*4*2*32) return;
    int lane = u & 31;
    int term = (u >> 5) & 1;
    int ks   = (u >> 6) & 3;
    int ct   = u >> 8;
    int col = ct*8 + (lane >> 2);
    int f0  = ks*16 + (lane & 3)*2;
    __nv_bfloat16 e[4];
    #pragma unroll
    for (int r = 0; r < 4; r++) {
        int f = f0 + (r >> 1)*8 + (r & 1);
        float v = g_Wc[f*NH + col];
        __nv_bfloat16 hi = __float2bfloat16(v);
        e[r] = term ? __float2bfloat16(v - __bfloat162float(hi)) : hi;
    }
    uint32_t b0 = bpack(e[0], e[1]);
    uint32_t b1 = bpack(e[2], e[3]);
    g_Wfrag[u] = ((unsigned long long)b1 << 32) | b0;
}

// ---------------- persistent fused kernel ----------------
// smem (bytes):
//  sXa   @ 0      : 16 x 68 f32 token-major            4608 (4352 used)
//  sXb   @ 4608   : 16 x 68 f32                        4608
//  sCa1  @ 9216   : 1536 f32                           6144
//  sCa2  @ 15360  : 1536 f32                           6144
//  sCb1  @ 21504  : 24 f32                             96
//  sCb2  @ 21600  : 24 f32                             96
//  sF1   @ 21696  : 16x24 f32                          1536
//  sF2   @ 23232  : 16x24 f32                          1536
//  sAdj  @ 24768  : 576 i32                            2304
//  sAttn @ 27072  : 16x24x24 f32                       36864
//  sWh   @ 63936  : 16x1536 f32                        98304
//  sBC   @ 162240 : 1536 f32                           6144
#define SMEM_BYTES 168384

__global__ void __launch_bounds__(THR, 1)
k_main(const float* __restrict__ x, const int* __restrict__ adj,
       float* __restrict__ out) {
    extern __shared__ char smem[];
    float* sXbuf[2] = { (float*)(smem), (float*)(smem + 4608) };
    float* sCa1  = (float*)(smem + 9216);
    float* sCa2  = (float*)(smem + 15360);
    float* sCb1  = (float*)(smem + 21504);
    float* sCb2  = (float*)(smem + 21600);
    float* sF1   = (float*)(smem + 21696);
    float* sF2   = (float*)(smem + 23232);
    int*   sAdj  = (int*)  (smem + 24768);
    float* sAttn = (float*)(smem + 27072);
    float* sWh   = (float*)(smem + 63936);
    float* sBC   = (float*)(smem + 162240);

    const int tid = threadIdx.x;

    // ---- one-time loads ----
    for (int i = tid; i < FIN*NN; i += THR) { sCa1[i] = g_ca1[i]; sCa2[i] = g_ca2[i]; }
    for (int i = tid; i < NH;     i += THR) sBC[i] = g_bc[i];
    if (tid < NN) { sCb1[tid] = g_cb1[tid]; sCb2[tid] = g_cb2[tid]; }
    for (int i = tid; i < NN*NN; i += THR) sAdj[i] = adj[i];

    // ---- sX prefetch helper (inline): 16 tokens x 64 f32 = 256 x 16B chunks ----
    auto prefetch_sX = [&](float* dst, int tile) {
        if (tile < NTILE && tid < 256) {
            int t = tid >> 4, c = tid & 15;
            CP_ASYNC16(smem_u32(dst + t*XS3 + c*4),
                       x + (size_t)(tile*TOK + t)*FIN + c*4);
        }
        CP_COMMIT();
    };

    int tile = blockIdx.x;
    int b = 0;
    prefetch_sX(sXbuf[0], tile);

    for (; tile < NTILE; tile += PGRID, b ^= 1) {
        prefetch_sX(sXbuf[b ^ 1], tile + PGRID);
        CP_WAIT1();                 // current buffer landed (newest group still in flight)
        __syncthreads();            // also orders prev tile's phase-2 before sWh/sAttn reuse
        const float* sX = sXbuf[b];
        const int tok0 = tile * TOK;

        // ---- f1/f2: 16 tokens x 24 nodes (warps 0-11) ----
        if (tid < TOK*NN) {
            int t = tid / NN, n = tid % NN;
            float s1 = sCb1[n], s2 = sCb2[n];
            #pragma unroll 8
            for (int f = 0; f < FIN; f++) {
                float xv = sX[t*XS3 + f];
                s1 = fmaf(xv, sCa1[f*NN + n], s1);
                s2 = fmaf(xv, sCa2[f*NN + n], s2);
            }
            sF1[t*NN + n] = s1;
            sF2[t*NN + n] = s2;
        }
        __syncthreads();

        // ---- softmax rows (warps 0-11); warps 12-15 run ahead into phase-1 ----
        if (tid < TOK*NN) {
            int t = tid / NN, i = tid % NN;
            float f1v = sF1[t*NN + i];
            float ev[NN];
            float m = -3.0e38f;
            #pragma unroll
            for (int j = 0; j < NN; j++) {
                float e = f1v + sF2[t*NN + j];
                e = e > 0.f ? e : ALPHA * e;
                e = (sAdj[i*NN + j] > 0) ? e : NEGINF;
                ev[j] = e;
                m = fmaxf(m, e);
            }
            float sum = 0.f;
            #pragma unroll
            for (int j = 0; j < NN; j++) { float p = __expf(ev[j] - m); ev[j] = p; sum += p; }
            float inv = 1.0f / sum;
            #pragma unroll
            for (int j = 0; j < NN; j++) sAttn[t*576 + i*NN + j] = ev[j] * inv;
        }

        // ---- phase 1: Wh = x @ Wc + bc (mma, 3-term bf16 split, pipelined frags) ----
        {
            const int w = tid >> 5, lane = tid & 31;
            const int t0 = lane >> 2;
            const int fq = (lane & 3) * 2;
            const int ctb = w*12;

            // A fragments (hi/lo) — v0/v1 contiguous in token-major sX -> one LDS.64
            uint32_t ah[4][4], al[4][4];
            #pragma unroll
            for (int ks = 0; ks < 4; ks++) {
                #pragma unroll
                for (int r = 0; r < 4; r++) {
                    int f = ks*16 + fq + (r >> 1)*8;
                    int t = t0 + (r & 1)*8;
                    float2 v = *(const float2*)&sX[t*XS3 + f];
                    __nv_bfloat16 h0 = __float2bfloat16(v.x);
                    __nv_bfloat16 h1 = __float2bfloat16(v.y);
                    ah[ks][r] = bpack(h0, h1);
                    al[ks][r] = bpack(__float2bfloat16(v.x - __bfloat162float(h0)),
                                      __float2bfloat16(v.y - __bfloat162float(h1)));
                }
            }

            // depth-1 pipelined fragment loads
            unsigned long long fb[2][8];     // [buf][ks*2 + term]
            #pragma unroll
            for (int ks = 0; ks < 4; ks++) {
                fb[0][ks*2]   = __ldg(&g_Wfrag[((ctb*4 + ks)*2 + 0)*32 + lane]);
                fb[0][ks*2+1] = __ldg(&g_Wfrag[((ctb*4 + ks)*2 + 1)*32 + lane]);
            }
            #pragma unroll
            for (int nt = 0; nt < 12; nt++) {
                const int cb = nt & 1, pb = cb ^ 1;
                if (nt < 11) {
                    const int ct2 = ctb + nt + 1;
                    #pragma unroll
                    for (int ks = 0; ks < 4; ks++) {
                        fb[pb][ks*2]   = __ldg(&g_Wfrag[((ct2*4 + ks)*2 + 0)*32 + lane]);
                        fb[pb][ks*2+1] = __ldg(&g_Wfrag[((ct2*4 + ks)*2 + 1)*32 + lane]);
                    }
                }
                float d0 = 0.f, d1 = 0.f, d2 = 0.f, d3 = 0.f;
                #pragma unroll
                for (int ks = 0; ks < 4; ks++) {
                    uint32_t bh0, bh1, bl0, bl1;
                    unpack2u(fb[cb][ks*2],   bh0, bh1);
                    unpack2u(fb[cb][ks*2+1], bl0, bl1);
                    mma16816(d0, d1, d2, d3, ah[ks][0], ah[ks][1], ah[ks][2], ah[ks][3], bh0, bh1);
                    mma16816(d0, d1, d2, d3, ah[ks][0], ah[ks][1], ah[ks][2], ah[ks][3], bl0, bl1);
                    mma16816(d0, d1, d2, d3, al[ks][0], al[ks][1], al[ks][2], al[ks][3], bh0, bh1);
                }
                const int col = (ctb + nt)*8 + fq;
                float b0 = sBC[col], b1 = sBC[col + 1];
                *(unsigned long long*)&sWh[t0*NH + col]     = pack2(d0 + b0, d1 + b1);
                *(unsigned long long*)&sWh[(t0+8)*NH + col] = pack2(d2 + b0, d3 + b1);
            }
        }
        __syncthreads();

        // ---- phase 2: out[t][k] = mean_i elu( sum_j attn[t][i][j]*Wh[t][j][k] ) ----
        {
            const int t = tid >> 5;        // token (uniform per warp)
            const int g = tid & 31;        // k in {g, g+32}
            const float* whb = sWh + (size_t)t*NH;
            unsigned long long wj[12][2];
            #pragma unroll
            for (int m = 0; m < 12; m++) {
                wj[m][0] = pack2(whb[(2*m)*HH + g],      whb[(2*m+1)*HH + g]);
                wj[m][1] = pack2(whb[(2*m)*HH + g + 32], whb[(2*m+1)*HH + g + 32]);
            }
            const unsigned long long* ap = (const unsigned long long*)(sAttn + t*576);
            float o0 = 0.f, o1 = 0.f;
            #pragma unroll 2
            for (int i = 0; i < NN; i++) {
                unsigned long long s0 = 0ull, s1 = 0ull;
                #pragma unroll
                for (int m = 0; m < 12; m++) {
                    unsigned long long av = ap[i*12 + m];
                    FMA2(s0, av, wj[m][0]);
                    FMA2(s1, av, wj[m][1]);
                }
                float a0, b0, a1, b1;
                unpack2(s0, a0, b0);
                unpack2(s1, a1, b1);
                float v0 = a0 + b0, v1 = a1 + b1;
                o0 += (v0 > 0.f) ? v0 : (__expf(v0) - 1.f);
                o1 += (v1 > 0.f) ? v1 : (__expf(v1) - 1.f);
            }
            const float sc = 1.0f / (float)NN;
            float* ob = out + (size_t)(tok0 + t) * HH;
            ob[g]      = o0 * sc;
            ob[g + 32] = o1 * sc;
        }
        // no sync here: next-iter top __syncthreads covers sWh/sAttn reuse;
        // next-iter sX prefetch only touches the buffer unread since last phase-1.
    }
}

// ---------------- launch ----------------
extern "C" void kernel_launch(void* const* d_in, const int* in_sizes, int n_in,
                              void* d_out, int out_size) {
    const float* x   = (const float*)d_in[0];
    const int*   adj = (const int*)  d_in[1];
    const float* Wp  = (const float*)d_in[2];
    const float* bp  = (const float*)d_in[3];
    const float* W   = (const float*)d_in[4];
    const float* a   = (const float*)d_in[5];
    float* out = (float*)d_out;

    k_pre<<<dim3(FIN, 4), 256>>>(Wp, bp, W, a);
    k_frag<<<192, 256>>>();

    cudaFuncSetAttribute(k_main, cudaFuncAttributeMaxDynamicSharedMemorySize, SMEM_BYTES);
    k_main<<<PGRID, THR, SMEM_BYTES>>>(x, adj, out);
}

// round 14
// speedup vs baseline: 1.5893x; 1.1064x over previous
#include <cuda_runtime.h>
#include <cuda_bf16.h>
#include <cuda_fp16.h>
#include <cstdint>

// Problem constants
#define NB   16
#define TT   2048
#define FIN  64
#define NN   24
#define HH   64
#define BT   (NB*TT)            // 32768
#define NH   (NN*HH)            // 1536
#define TOK  16                 // tokens per tile
#define THR  512
#define NTILE (BT/TOK)          // 2048
#define PGRID 152               // persistent blocks
#define ALPHA 0.2f
#define NEGINF (-9.0e15f)
#define XS3  68                 // token-major sX row stride

// ---------------- device globals (no allocs) ----------------
__device__ __align__(16) float g_Wc[FIN*NH];    // [f][col], col = n*64+k
__device__ __align__(16) float g_bc[NH];
__device__ __align__(16) float g_ca1[FIN*NN];
__device__ __align__(16) float g_ca2[FIN*NN];
__device__ float g_cb1[NN];
__device__ float g_cb2[NN];
// B fragments for mma.m16n8k16 fp16, single term (fp16(Wc)), fragment-ordered:
// index = (ct*4 + ks)*32 + lane, each 8B = {b0, b1}
__device__ __align__(16) unsigned long long g_Wfrag[192*4*32];   // 192KB

// ---------------- packed fp32x2 helpers ----------------
__device__ __forceinline__ unsigned long long pack2(float lo, float hi) {
    unsigned long long r;
    asm("mov.b64 %0, {%1, %2};" : "=l"(r) : "f"(lo), "f"(hi));
    return r;
}
__device__ __forceinline__ void unpack2u(unsigned long long v, uint32_t& lo, uint32_t& hi) {
    asm("mov.b64 {%0, %1}, %2;" : "=r"(lo), "=r"(hi) : "l"(v));
}
__device__ __forceinline__ void unpack2(unsigned long long v, float& lo, float& hi) {
    asm("mov.b64 {%0, %1}, %2;" : "=f"(lo), "=f"(hi) : "l"(v));
}
#define FMA2(acc, a, b) asm("fma.rn.f32x2 %0, %1, %2, %0;" : "+l"(acc) : "l"(a), "l"(b))

// ---------------- warp mma m16n8k16 fp16 (f32 accum) ----------------
__device__ __forceinline__ void mma16816(float& d0, float& d1, float& d2, float& d3,
                                         uint32_t a0, uint32_t a1, uint32_t a2, uint32_t a3,
                                         uint32_t b0, uint32_t b1) {
    asm("mma.sync.aligned.m16n8k16.row.col.f32.f16.f16.f32 "
        "{%0,%1,%2,%3}, {%4,%5,%6,%7}, {%8,%9}, {%0,%1,%2,%3};"
        : "+f"(d0), "+f"(d1), "+f"(d2), "+f"(d3)
        : "r"(a0), "r"(a1), "r"(a2), "r"(a3), "r"(b0), "r"(b1));
}
__device__ __forceinline__ uint32_t hpack(__half x, __half y) {
    __half2 p; p.x = x; p.y = y;
    return *(uint32_t*)&p;
}

// ---------------- cp.async ----------------
__device__ __forceinline__ uint32_t smem_u32(const void* p) {
    return (uint32_t)__cvta_generic_to_shared(p);
}
#define CP_ASYNC16(dst, src) \
    asm volatile("cp.async.cg.shared.global [%0], [%1], 16;" :: "r"(dst), "l"(src) : "memory")
#define CP_COMMIT() asm volatile("cp.async.commit_group;" ::: "memory")
#define CP_WAIT1()  asm volatile("cp.async.wait_group 1;" ::: "memory")

// ---------------- precompute: grid (64, 4), 4-way ILP dot products ----------------
__global__ void __launch_bounds__(256)
k_pre(const float* __restrict__ Wp, const float* __restrict__ bp,
      const float* __restrict__ W,  const float* __restrict__ a) {
    __shared__ float sW[HH*HH];
    __shared__ float sWp[NH];
    __shared__ float swa1[HH], swa2[HH];
    const int f = blockIdx.x, q = blockIdx.y, tid = threadIdx.x;
    for (int i = tid; i < HH*HH; i += 256) sW[i] = W[i];
    for (int i = tid; i < NH;    i += 256) sWp[i] = Wp[f*NH + i];
    __syncthreads();
    if (q == 0 && tid < HH) {
        float s1 = 0.f, s2 = 0.f, s3 = 0.f, s4 = 0.f;
        #pragma unroll
        for (int k = 0; k < HH; k += 2) {
            float w0 = sW[tid*HH + k], w1 = sW[tid*HH + k + 1];
            s1 = fmaf(w0, a[k],        s1);
            s3 = fmaf(w1, a[k+1],      s3);
            s2 = fmaf(w0, a[HH+k],     s2);
            s4 = fmaf(w1, a[HH+k+1],   s4);
        }
        swa1[tid] = s1 + s3; swa2[tid] = s2 + s4;
    }
    __syncthreads();
    for (int o = q*384 + tid; o < q*384 + 384; o += 256) {
        int n = o >> 6, k = o & 63;
        float s0 = 0.f, s1 = 0.f, s2 = 0.f, s3 = 0.f;
        #pragma unroll
        for (int j = 0; j < HH; j += 4) {
            s0 = fmaf(sWp[n*HH + j],     sW[(j)*HH + k],   s0);
            s1 = fmaf(sWp[n*HH + j + 1], sW[(j+1)*HH + k], s1);
            s2 = fmaf(sWp[n*HH + j + 2], sW[(j+2)*HH + k], s2);
            s3 = fmaf(sWp[n*HH + j + 3], sW[(j+3)*HH + k], s3);
        }
        g_Wc[f*NH + o] = (s0 + s1) + (s2 + s3);
    }
    if (q == 0) {
        if (tid < NN) {
            float s1 = 0.f, s2 = 0.f, s3 = 0.f, s4 = 0.f;
            #pragma unroll
            for (int j = 0; j < HH; j += 2) {
                float w0 = sWp[tid*HH + j], w1 = sWp[tid*HH + j + 1];
                s1 = fmaf(w0, swa1[j],   s1);
                s3 = fmaf(w1, swa1[j+1], s3);
                s2 = fmaf(w0, swa2[j],   s2);
                s4 = fmaf(w1, swa2[j+1], s4);
            }
            g_ca1[f*NN + tid] = s1 + s3;
            g_ca2[f*NN + tid] = s2 + s4;
        }
        if (tid >= 32 && tid < 32 + NN) {
            int c = f*NN + (tid - 32);
            int n = c >> 6, k = c & 63;
            float s0 = 0.f, s1 = 0.f;
            #pragma unroll
            for (int j = 0; j < HH; j += 2) {
                s0 = fmaf(bp[n*HH + j],     sW[(j)*HH + k],   s0);
                s1 = fmaf(bp[n*HH + j + 1], sW[(j+1)*HH + k], s1);
            }
            g_bc[c] = s0 + s1;
        }
        if (f == 0 && tid >= 64 && tid < 64 + NN) {
            int n = tid - 64;
            float s1 = 0.f, s2 = 0.f;
            for (int j = 0; j < HH; j++) {
                float b = bp[n*HH + j];
                s1 = fmaf(b, swa1[j], s1);
                s2 = fmaf(b, swa2[j], s2);
            }
            g_cb1[n] = s1; g_cb2[n] = s2;
        }
    }
}

// ---------------- B-fragment precompute: single fp16 term ----------------
// u: lane=u&31, ks=(u>>5)&3, ct=u>>7
// col = ct*8 + lane/4, f0 = ks*16 + (lane%4)*2, f = f0 + (r>>1)*8 + (r&1)
__global__ void k_frag() {
    int u = blockIdx.x * 256 + threadIdx.x;
    if (u >= 192*4*32) return;
    int lane = u & 31;
    int ks   = (u >> 5) & 3;
    int ct   = u >> 7;
    int col = ct*8 + (lane >> 2);
    int f0  = ks*16 + (lane & 3)*2;
    __half e[4];
    #pragma unroll
    for (int r = 0; r < 4; r++) {
        int f = f0 + (r >> 1)*8 + (r & 1);
        e[r] = __float2half(g_Wc[f*NH + col]);
    }
    uint32_t b0 = hpack(e[0], e[1]);
    uint32_t b1 = hpack(e[2], e[3]);
    g_Wfrag[u] = ((unsigned long long)b1 << 32) | b0;
}

// ---------------- persistent fused kernel ----------------
// smem (bytes):
//  sXa   @ 0      : 16 x 68 f32 token-major            4608
//  sXb   @ 4608   : 16 x 68 f32                        4608
//  sCa1  @ 9216   : 1536 f32                           6144
//  sCa2  @ 15360  : 1536 f32                           6144
//  sCb1  @ 21504  : 24 f32                             96
//  sCb2  @ 21600  : 24 f32                             96
//  sF1   @ 21696  : 16x24 f32                          1536
//  sF2   @ 23232  : 16x24 f32                          1536
//  sAdj  @ 24768  : 576 i32                            2304
//  sAttn @ 27072  : 16x24x24 f32                       36864
//  sWh   @ 63936  : 16x1536 f32                        98304
//  sBC   @ 162240 : 1536 f32                           6144
#define SMEM_BYTES 168384

__global__ void __launch_bounds__(THR, 1)
k_main(const float* __restrict__ x, const int* __restrict__ adj,
       float* __restrict__ out) {
    extern __shared__ char smem[];
    float* sXbuf[2] = { (float*)(smem), (float*)(smem + 4608) };
    float* sCa1  = (float*)(smem + 9216);
    float* sCa2  = (float*)(smem + 15360);
    float* sCb1  = (float*)(smem + 21504);
    float* sCb2  = (float*)(smem + 21600);
    float* sF1   = (float*)(smem + 21696);
    float* sF2   = (float*)(smem + 23232);
    int*   sAdj  = (int*)  (smem + 24768);
    float* sAttn = (float*)(smem + 27072);
    float* sWh   = (float*)(smem + 63936);
    float* sBC   = (float*)(smem + 162240);

    const int tid = threadIdx.x;

    // ---- one-time loads ----
    for (int i = tid; i < FIN*NN; i += THR) { sCa1[i] = g_ca1[i]; sCa2[i] = g_ca2[i]; }
    for (int i = tid; i < NH;     i += THR) sBC[i] = g_bc[i];
    if (tid < NN) { sCb1[tid] = g_cb1[tid]; sCb2[tid] = g_cb2[tid]; }
    for (int i = tid; i < NN*NN; i += THR) sAdj[i] = adj[i];

    auto prefetch_sX = [&](float* dst, int tile) {
        if (tile < NTILE && tid < 256) {
            int t = tid >> 4, c = tid & 15;
            CP_ASYNC16(smem_u32(dst + t*XS3 + c*4),
                       x + (size_t)(tile*TOK + t)*FIN + c*4);
        }
        CP_COMMIT();
    };

    int tile = blockIdx.x;
    int b = 0;
    prefetch_sX(sXbuf[0], tile);

    for (; tile < NTILE; tile += PGRID, b ^= 1) {
        prefetch_sX(sXbuf[b ^ 1], tile + PGRID);
        CP_WAIT1();
        __syncthreads();
        const float* sX = sXbuf[b];
        const int tok0 = tile * TOK;

        // ---- f1/f2 ----
        if (tid < TOK*NN) {
            int t = tid / NN, n = tid % NN;
            float s1 = sCb1[n], s2 = sCb2[n];
            #pragma unroll 8
            for (int f = 0; f < FIN; f++) {
                float xv = sX[t*XS3 + f];
                s1 = fmaf(xv, sCa1[f*NN + n], s1);
                s2 = fmaf(xv, sCa2[f*NN + n], s2);
            }
            sF1[t*NN + n] = s1;
            sF2[t*NN + n] = s2;
        }
        __syncthreads();

        // ---- softmax rows (warps 0-11); warps 12-15 run ahead into phase-1 ----
        if (tid < TOK*NN) {
            int t = tid / NN, i = tid % NN;
            float f1v = sF1[t*NN + i];
            float ev[NN];
            float m = -3.0e38f;
            #pragma unroll
            for (int j = 0; j < NN; j++) {
                float e = f1v + sF2[t*NN + j];
                e = e > 0.f ? e : ALPHA * e;
                e = (sAdj[i*NN + j] > 0) ? e : NEGINF;
                ev[j] = e;
                m = fmaxf(m, e);
            }
            float sum = 0.f;
            #pragma unroll
            for (int j = 0; j < NN; j++) { float p = __expf(ev[j] - m); ev[j] = p; sum += p; }
            float inv = 1.0f / sum;
            #pragma unroll
            for (int j = 0; j < NN; j++) sAttn[t*576 + i*NN + j] = ev[j] * inv;
        }

        // ---- phase 1: Wh = x @ Wc + bc (mma fp16, 2-term x-split, pipelined frags) ----
        {
            const int w = tid >> 5, lane = tid & 31;
            const int t0 = lane >> 2;
            const int fq = (lane & 3) * 2;
            const int ctb = w*12;

            // A fragments: xh (fp16 of x) and xl (fp16 of residual)
            uint32_t ah[4][4], al[4][4];
            #pragma unroll
            for (int ks = 0; ks < 4; ks++) {
                #pragma unroll
                for (int r = 0; r < 4; r++) {
                    int f = ks*16 + fq + (r >> 1)*8;
                    int t = t0 + (r & 1)*8;
                    float2 v = *(const float2*)&sX[t*XS3 + f];
                    __half h0 = __float2half(v.x);
                    __half h1 = __float2half(v.y);
                    ah[ks][r] = hpack(h0, h1);
                    al[ks][r] = hpack(__float2half(v.x - __half2float(h0)),
                                      __float2half(v.y - __half2float(h1)));
                }
            }

            // depth-1 pipelined fragment loads (4 longs per nt)
            unsigned long long fb[2][4];
            #pragma unroll
            for (int ks = 0; ks < 4; ks++)
                fb[0][ks] = __ldg(&g_Wfrag[(ctb*4 + ks)*32 + lane]);
            #pragma unroll
            for (int nt = 0; nt < 12; nt++) {
                const int cb = nt & 1, pb = cb ^ 1;
                if (nt < 11) {
                    const int ct2 = ctb + nt + 1;
                    #pragma unroll
                    for (int ks = 0; ks < 4; ks++)
                        fb[pb][ks] = __ldg(&g_Wfrag[(ct2*4 + ks)*32 + lane]);
                }
                float d0 = 0.f, d1 = 0.f, d2 = 0.f, d3 = 0.f;
                #pragma unroll
                for (int ks = 0; ks < 4; ks++) {
                    uint32_t b0, b1;
                    unpack2u(fb[cb][ks], b0, b1);
                    mma16816(d0, d1, d2, d3, ah[ks][0], ah[ks][1], ah[ks][2], ah[ks][3], b0, b1);
                    mma16816(d0, d1, d2, d3, al[ks][0], al[ks][1], al[ks][2], al[ks][3], b0, b1);
                }
                const int col = (ctb + nt)*8 + fq;
                float b0 = sBC[col], b1 = sBC[col + 1];
                *(unsigned long long*)&sWh[t0*NH + col]     = pack2(d0 + b0, d1 + b1);
                *(unsigned long long*)&sWh[(t0+8)*NH + col] = pack2(d2 + b0, d3 + b1);
            }
        }
        __syncthreads();

        // ---- phase 2: out[t][k] = mean_i elu( sum_j attn[t][i][j]*Wh[t][j][k] ) ----
        {
            const int t = tid >> 5;
            const int g = tid & 31;
            const float* whb = sWh + (size_t)t*NH;
            unsigned long long wj[12][2];
            #pragma unroll
            for (int m = 0; m < 12; m++) {
                wj[m][0] = pack2(whb[(2*m)*HH + g],      whb[(2*m+1)*HH + g]);
                wj[m][1] = pack2(whb[(2*m)*HH + g + 32], whb[(2*m+1)*HH + g + 32]);
            }
            const unsigned long long* ap = (const unsigned long long*)(sAttn + t*576);
            float o0 = 0.f, o1 = 0.f;
            #pragma unroll 2
            for (int i = 0; i < NN; i++) {
                unsigned long long s0 = 0ull, s1 = 0ull;
                #pragma unroll
                for (int m = 0; m < 12; m++) {
                    unsigned long long av = ap[i*12 + m];
                    FMA2(s0, av, wj[m][0]);
                    FMA2(s1, av, wj[m][1]);
                }
                float a0, b0, a1, b1;
                unpack2(s0, a0, b0);
                unpack2(s1, a1, b1);
                float v0 = a0 + b0, v1 = a1 + b1;
                o0 += (v0 > 0.f) ? v0 : (__expf(v0) - 1.f);
                o1 += (v1 > 0.f) ? v1 : (__expf(v1) - 1.f);
            }
            const float sc = 1.0f / (float)NN;
            float* ob = out + (size_t)(tok0 + t) * HH;
            ob[g]      = o0 * sc;
            ob[g + 32] = o1 * sc;
        }
    }
}

// ---------------- launch ----------------
extern "C" void kernel_launch(void* const* d_in, const int* in_sizes, int n_in,
                              void* d_out, int out_size) {
    const float* x   = (const float*)d_in[0];
    const int*   adj = (const int*)  d_in[1];
    const float* Wp  = (const float*)d_in[2];
    const float* bp  = (const float*)d_in[3];
    const float* W   = (const float*)d_in[4];
    const float* a   = (const float*)d_in[5];
    float* out = (float*)d_out;

    k_pre<<<dim3(FIN, 4), 256>>>(Wp, bp, W, a);
    k_frag<<<96, 256>>>();

    cudaFuncSetAttribute(k_main, cudaFuncAttributeMaxDynamicSharedMemorySize, SMEM_BYTES);
    k_main<<<PGRID, THR, SMEM_BYTES>>>(x, adj, out);
}